// round 5
// baseline (speedup 1.0000x reference)
#include <cuda_runtime.h>
#include <cstdint>

#define N_NODES 50000
#define MAX_E   800000
#define DIM_IN  128
#define DIM_HID 256
#define DIM_OUT 128

// ---------------- scratch (static __device__, allocation-free) ----------------
__device__ int   g_is64;
__device__ int   g_cnt[N_NODES];
__device__ int   g_row[N_NODES + 1];
__device__ int   g_cursor[N_NODES];
__device__ int   g_csr_src[MAX_E];
__device__ float g_dinv[N_NODES];
__device__ float g_buf128[(size_t)N_NODES * 128];   // agg1, then t = a1 @ W2
__device__ float g_a1[(size_t)N_NODES * 256];       // relu layer-1 activations

// ---------------- edge-index dtype detection + decode ----------------
// int64 indices < 50000 (little-endian): every odd 32-bit word is 0.
// int32 random indices: probability all 32 odd words are 0 is ~(2e-5)^32.
__global__ void k_detect(const int* __restrict__ ei) {
    if (threadIdx.x == 0) {
        int is64 = 1;
        for (int i = 1; i < 64; i += 2) {
            if (ei[i] != 0) { is64 = 0; break; }
        }
        g_is64 = is64;
    }
}

__device__ __forceinline__ int edge_idx(const void* __restrict__ ei, long long pos) {
    if (g_is64) return (int)((const long long*)ei)[pos];
    return ((const int*)ei)[pos];
}

// ---------------- CSR build ----------------
__global__ void k_zero_cnt() {
    int i = blockIdx.x * blockDim.x + threadIdx.x;
    if (i < N_NODES) g_cnt[i] = 0;
}

__global__ void k_hist(const void* __restrict__ ei, int E) {
    int e = blockIdx.x * blockDim.x + threadIdx.x;
    if (e >= E) return;
    int d = edge_idx(ei, (long long)E + e);
    if ((unsigned)d < N_NODES) atomicAdd(&g_cnt[d], 1);
}

// Single-block scan over 50k counters. Also emits cursor copy and dinv.
__global__ void k_scan() {
    const int CH = (N_NODES + 1023) / 1024;  // 49 elements per thread
    int t = threadIdx.x;
    int lane = t & 31, wid = t >> 5;
    int base = t * CH;

    int s = 0;
    for (int i = 0; i < CH; i++) {
        int idx = base + i;
        if (idx < N_NODES) s += g_cnt[idx];
    }
    int v = s;
    #pragma unroll
    for (int o = 1; o < 32; o <<= 1) {
        int u = __shfl_up_sync(0xffffffff, v, o);
        if (lane >= o) v += u;
    }
    __shared__ int wsum[32];
    if (lane == 31) wsum[wid] = v;
    __syncthreads();
    if (wid == 0) {
        int w = wsum[lane];
        #pragma unroll
        for (int o = 1; o < 32; o <<= 1) {
            int u = __shfl_up_sync(0xffffffff, w, o);
            if (lane >= o) w += u;
        }
        wsum[lane] = w;
    }
    __syncthreads();
    int excl = v - s + (wid > 0 ? wsum[wid - 1] : 0);

    int run = excl;
    for (int i = 0; i < CH; i++) {
        int idx = base + i;
        if (idx < N_NODES) {
            g_row[idx] = run;
            g_cursor[idx] = run;
            int c = g_cnt[idx];
            g_dinv[idx] = rsqrtf((float)(c + 1));  // +1 self-loop
            run += c;
        }
    }
    if (t == 1023) g_row[N_NODES] = run;
}

__global__ void k_scatter(const void* __restrict__ ei, int E) {
    int e = blockIdx.x * blockDim.x + threadIdx.x;
    if (e >= E) return;
    int s = edge_idx(ei, e);
    int d = edge_idx(ei, (long long)E + e);
    if ((unsigned)d >= N_NODES || (unsigned)s >= N_NODES) return;
    int pos = atomicAdd(&g_cursor[d], 1);
    g_csr_src[pos] = s;
}

// ---------------- pull aggregation: out[d] = sum_{s in N(d)} feat[s]*dinv[s]*dinv[d]
//                                           + feat[d]*dinv[d]^2 (+bias) ----------------
// One warp per node, one float4 per lane (128 features).
template <bool BIAS>
__global__ void k_agg_csr(const float* __restrict__ feat, float* __restrict__ out,
                          const float* __restrict__ bias) {
    int t = blockIdx.x * blockDim.x + threadIdx.x;
    int d = t >> 5;
    if (d >= N_NODES) return;
    int lane = t & 31;

    float dd = g_dinv[d];
    float4 v = ((const float4*)feat)[(size_t)d * 32 + lane];
    float sl = dd * dd;
    float4 acc;
    acc.x = v.x * sl; acc.y = v.y * sl; acc.z = v.z * sl; acc.w = v.w * sl;

    int beg = g_row[d], end = g_row[d + 1];
    for (int j = beg; j < end; j++) {
        int s = __ldg(&g_csr_src[j]);
        float norm = __ldg(&g_dinv[s]) * dd;
        float4 f = ((const float4*)feat)[(size_t)s * 32 + lane];
        acc.x = fmaf(f.x, norm, acc.x);
        acc.y = fmaf(f.y, norm, acc.y);
        acc.z = fmaf(f.z, norm, acc.z);
        acc.w = fmaf(f.w, norm, acc.w);
    }
    if (BIAS) {
        float4 b = ((const float4*)bias)[lane];
        acc.x += b.x; acc.y += b.y; acc.z += b.z; acc.w += b.w;
    }
    ((float4*)out)[(size_t)d * 32 + lane] = acc;
}

// ---------------- SGEMM: C = A[M,K] @ B[K,N] (+bias) (+relu) ----------------
// BM=64, BN=64, BK=16, 256 threads, 4x4 microtile per thread.
template <bool RELU, bool BIAS>
__global__ void k_gemm(const float* __restrict__ A, const float* __restrict__ B,
                       const float* __restrict__ bias, float* __restrict__ C,
                       int M, int K, int N) {
    __shared__ float As[16][68];   // [k][m], padded
    __shared__ float Bs[16][64];   // [k][n]

    int tid = threadIdx.x;
    int tx = tid & 15;
    int ty = tid >> 4;
    int bm = blockIdx.y * 64;
    int bn = blockIdx.x * 64;

    int arow  = tid >> 2;          // 0..63
    int acol4 = tid & 3;           // k offset = acol4*4
    int brow = tid >> 4;           // 0..15
    int bcol = (tid & 15) * 4;     // 0..60

    float acc[4][4] = {};

    for (int k0 = 0; k0 < K; k0 += 16) {
        float4 av = make_float4(0.f, 0.f, 0.f, 0.f);
        int gr = bm + arow;
        if (gr < M)
            av = *(const float4*)(A + (size_t)gr * K + k0 + acol4 * 4);
        As[acol4 * 4 + 0][arow] = av.x;
        As[acol4 * 4 + 1][arow] = av.y;
        As[acol4 * 4 + 2][arow] = av.z;
        As[acol4 * 4 + 3][arow] = av.w;

        float4 bv = *(const float4*)(B + (size_t)(k0 + brow) * N + bn + bcol);
        *(float4*)&Bs[brow][bcol] = bv;

        __syncthreads();

        #pragma unroll
        for (int k = 0; k < 16; k++) {
            float a[4], b[4];
            #pragma unroll
            for (int i = 0; i < 4; i++) a[i] = As[k][ty * 4 + i];
            #pragma unroll
            for (int j = 0; j < 4; j++) b[j] = Bs[k][tx * 4 + j];
            #pragma unroll
            for (int i = 0; i < 4; i++)
                #pragma unroll
                for (int j = 0; j < 4; j++)
                    acc[i][j] = fmaf(a[i], b[j], acc[i][j]);
        }
        __syncthreads();
    }

    #pragma unroll
    for (int i = 0; i < 4; i++) {
        int r = bm + ty * 4 + i;
        if (r >= M) continue;
        #pragma unroll
        for (int j = 0; j < 4; j++) {
            int c = bn + tx * 4 + j;
            float v = acc[i][j];
            if (BIAS) v += bias[c];
            if (RELU) v = fmaxf(v, 0.0f);
            C[(size_t)r * N + c] = v;
        }
    }
}

// ---------------- launch ----------------
extern "C" void kernel_launch(void* const* d_in, const int* in_sizes, int n_in,
                              void* d_out, int out_size) {
    const float* x  = (const float*)d_in[0];
    const void*  ei = d_in[1];                 // int32 or int64 — detected on device
    const float* W1 = (const float*)d_in[2];
    const float* b1 = (const float*)d_in[3];
    const float* W2 = (const float*)d_in[4];
    const float* b2 = (const float*)d_in[5];
    float*       out = (float*)d_out;

    const int E = in_sizes[1] / 2;

    float *buf128 = nullptr, *a1 = nullptr;
    cudaGetSymbolAddress((void**)&buf128, g_buf128);
    cudaGetSymbolAddress((void**)&a1, g_a1);

    // dtype sniff + CSR build (by destination) + dinv
    k_detect<<<1, 32>>>((const int*)ei);
    k_zero_cnt<<<(N_NODES + 255) / 256, 256>>>();
    k_hist<<<(E + 255) / 256, 256>>>(ei, E);
    k_scan<<<1, 1024>>>();
    k_scatter<<<(E + 255) / 256, 256>>>(ei, E);

    const int agg_blocks = (N_NODES * 32 + 255) / 256;

    // ---- layer 1: agg1 = S x ; a1 = relu(agg1 @ W1 + b1) ----
    k_agg_csr<false><<<agg_blocks, 256>>>(x, buf128, nullptr);
    {
        dim3 grid(DIM_HID / 64, (N_NODES + 63) / 64);
        k_gemm<true, true><<<grid, 256>>>(buf128, W1, b1, a1,
                                          N_NODES, DIM_IN, DIM_HID);
    }

    // ---- layer 2: t = a1 @ W2 ; out = S t + b2 ----
    {
        dim3 grid(DIM_OUT / 64, (N_NODES + 63) / 64);
        k_gemm<false, false><<<grid, 256>>>(a1, W2, nullptr, buf128,
                                            N_NODES, DIM_HID, DIM_OUT);
    }
    k_agg_csr<true><<<agg_blocks, 256>>>(buf128, out, b2);
}

// round 6
// speedup vs baseline: 1.2195x; 1.2195x over previous
#include <cuda_runtime.h>
#include <cstdint>

#define N_NODES 50000
#define MAX_E   800000
#define DIM_IN  128
#define DIM_HID 256
#define DIM_OUT 128

#define SCAN_B  256
#define NPART   ((N_NODES + SCAN_B - 1) / SCAN_B)   // 196

// ---------------- scratch (static __device__, allocation-free) ----------------
__device__ int   g_is64;
__device__ int   g_cnt[N_NODES];
__device__ int   g_part[NPART];
__device__ int   g_partoff[NPART];
__device__ int   g_row[N_NODES + 1];
__device__ int   g_cursor[N_NODES];
__device__ int   g_csr_src[MAX_E];
__device__ float g_dinv[N_NODES];
__device__ float g_buf128[(size_t)N_NODES * 128];   // agg1, then t = a1 @ W2
__device__ float g_a1[(size_t)N_NODES * 256];       // relu layer-1 activations

// ---------------- edge-index dtype detection + decode ----------------
// int64 indices < 50000 (LE): every odd 32-bit word is 0.
__global__ void k_detect(const int* __restrict__ ei) {
    if (threadIdx.x == 0) {
        int is64 = 1;
        for (int i = 1; i < 64; i += 2) {
            if (ei[i] != 0) { is64 = 0; break; }
        }
        g_is64 = is64;
    }
}

__device__ __forceinline__ int edge_idx(const void* __restrict__ ei, long long pos) {
    if (g_is64) return (int)((const long long*)ei)[pos];
    return ((const int*)ei)[pos];
}

// ---------------- CSR build ----------------
__global__ void k_zero_cnt() {
    int i = blockIdx.x * blockDim.x + threadIdx.x;
    if (i < N_NODES) g_cnt[i] = 0;
}

__global__ void k_hist(const void* __restrict__ ei, int E) {
    int e = blockIdx.x * blockDim.x + threadIdx.x;
    if (e >= E) return;
    int d = edge_idx(ei, (long long)E + e);
    if ((unsigned)d < N_NODES) atomicAdd(&g_cnt[d], 1);
}

// phase 1: per-block sums of 256 counters
__global__ void k_part_sum() {
    int i = blockIdx.x * SCAN_B + threadIdx.x;
    int c = (i < N_NODES) ? g_cnt[i] : 0;
    // warp reduce then cross-warp
    for (int o = 16; o > 0; o >>= 1) c += __shfl_down_sync(0xffffffff, c, o);
    __shared__ int ws[8];
    int lane = threadIdx.x & 31, wid = threadIdx.x >> 5;
    if (lane == 0) ws[wid] = c;
    __syncthreads();
    if (wid == 0) {
        int v = (lane < 8) ? ws[lane] : 0;
        for (int o = 4; o > 0; o >>= 1) v += __shfl_down_sync(0xffffffff, v, o);
        if (lane == 0) g_part[blockIdx.x] = v;
    }
}

// phase 2: single tiny block scans 196 partials (exclusive)
__global__ void k_scan_part() {
    int t = threadIdx.x;                 // 256 threads
    int v = (t < NPART) ? g_part[t] : 0;
    int orig = v;
    int lane = t & 31, wid = t >> 5;
    #pragma unroll
    for (int o = 1; o < 32; o <<= 1) {
        int u = __shfl_up_sync(0xffffffff, v, o);
        if (lane >= o) v += u;
    }
    __shared__ int ws[8];
    if (lane == 31) ws[wid] = v;
    __syncthreads();
    if (wid == 0 && lane < 8) {
        int w = ws[lane];
        #pragma unroll
        for (int o = 1; o < 8; o <<= 1) {
            int u = __shfl_up_sync(0xff, w, o);
            if (lane >= o) w += u;
        }
        ws[lane] = w;
    }
    __syncthreads();
    int incl = v + (wid > 0 ? ws[wid - 1] : 0);
    if (t < NPART) g_partoff[t] = incl - orig;   // exclusive
}

// phase 3: per-block exclusive scan + fill row/cursor/dinv
__global__ void k_fill() {
    __shared__ int sh[SCAN_B];
    int b = blockIdx.x;
    int t = threadIdx.x;
    int i = b * SCAN_B + t;
    int c = (i < N_NODES) ? g_cnt[i] : 0;
    int v = c;
    int lane = t & 31, wid = t >> 5;
    #pragma unroll
    for (int o = 1; o < 32; o <<= 1) {
        int u = __shfl_up_sync(0xffffffff, v, o);
        if (lane >= o) v += u;
    }
    __shared__ int ws[8];
    if (lane == 31) ws[wid] = v;
    __syncthreads();
    if (wid == 0 && lane < 8) {
        int w = ws[lane];
        #pragma unroll
        for (int o = 1; o < 8; o <<= 1) {
            int u = __shfl_up_sync(0xff, w, o);
            if (lane >= o) w += u;
        }
        ws[lane] = w;
    }
    __syncthreads();
    int excl = v - c + (wid > 0 ? ws[wid - 1] : 0) + g_partoff[b];
    if (i < N_NODES) {
        g_row[i] = excl;
        g_cursor[i] = excl;
        g_dinv[i] = rsqrtf((float)(c + 1));   // +1 self-loop
        if (i == N_NODES - 1) g_row[N_NODES] = excl + c;
    }
    (void)sh;
}

__global__ void k_scatter(const void* __restrict__ ei, int E) {
    int e = blockIdx.x * blockDim.x + threadIdx.x;
    if (e >= E) return;
    int s = edge_idx(ei, e);
    int d = edge_idx(ei, (long long)E + e);
    if ((unsigned)d >= N_NODES || (unsigned)s >= N_NODES) return;
    int pos = atomicAdd(&g_cursor[d], 1);
    g_csr_src[pos] = s;
}

// ---------------- pull aggregation ----------------
// out[d] = sum_{s in N(d)} feat[s]*dinv[s]*dinv[d] + feat[d]*dinv[d]^2 (+bias)
// One warp per node, one float4 per lane (128 features).
template <bool BIAS>
__global__ void k_agg_csr(const float* __restrict__ feat, float* __restrict__ out,
                          const float* __restrict__ bias) {
    int t = blockIdx.x * blockDim.x + threadIdx.x;
    int d = t >> 5;
    if (d >= N_NODES) return;
    int lane = t & 31;

    float dd = g_dinv[d];
    float4 v = ((const float4*)feat)[(size_t)d * 32 + lane];
    float sl = dd * dd;
    float4 acc;
    acc.x = v.x * sl; acc.y = v.y * sl; acc.z = v.z * sl; acc.w = v.w * sl;

    int beg = g_row[d], end = g_row[d + 1];
    for (int j = beg; j < end; j++) {
        int s = __ldg(&g_csr_src[j]);
        float norm = __ldg(&g_dinv[s]) * dd;
        float4 f = ((const float4*)feat)[(size_t)s * 32 + lane];
        acc.x = fmaf(f.x, norm, acc.x);
        acc.y = fmaf(f.y, norm, acc.y);
        acc.z = fmaf(f.z, norm, acc.z);
        acc.w = fmaf(f.w, norm, acc.w);
    }
    if (BIAS) {
        float4 b = ((const float4*)bias)[lane];
        acc.x += b.x; acc.y += b.y; acc.z += b.z; acc.w += b.w;
    }
    ((float4*)out)[(size_t)d * 32 + lane] = acc;
}

// ---------------- SGEMM: C = A[M,K] @ B[K,N] (+bias) (+relu) ----------------
// BM=BN=128, BK=8, 256 threads, 8x8 microtile per thread.
template <bool RELU, bool BIAS>
__global__ void __launch_bounds__(256)
k_gemm128(const float* __restrict__ A, const float* __restrict__ B,
          const float* __restrict__ bias, float* __restrict__ C,
          int M, int K, int N) {
    __shared__ float As[8][132];   // [k][m], padded (132*4=528, 16B-aligned rows)
    __shared__ float Bs[8][128];   // [k][n]

    int tid = threadIdx.x;
    int tx = tid & 15;             // 0..15 -> col group (8 cols)
    int ty = tid >> 4;             // 0..15 -> row group (8 rows)
    int bm = blockIdx.y * 128;
    int bn = blockIdx.x * 128;

    // A load: 128 rows x 8 k = 1024 floats -> float4/thread
    int ar = tid >> 1;             // 0..127
    int ak = (tid & 1) * 4;        // 0 or 4
    // B load: 8 k-rows x 128 cols = 1024 floats -> float4/thread
    int br = tid >> 5;             // 0..7
    int bc = (tid & 31) * 4;       // 0..124

    float acc[8][8] = {};

    for (int k0 = 0; k0 < K; k0 += 8) {
        float4 av = make_float4(0.f, 0.f, 0.f, 0.f);
        int gr = bm + ar;
        if (gr < M)
            av = *(const float4*)(A + (size_t)gr * K + k0 + ak);
        As[ak + 0][ar] = av.x;
        As[ak + 1][ar] = av.y;
        As[ak + 2][ar] = av.z;
        As[ak + 3][ar] = av.w;

        *(float4*)&Bs[br][bc] = *(const float4*)(B + (size_t)(k0 + br) * N + bn + bc);

        __syncthreads();

        #pragma unroll
        for (int k = 0; k < 8; k++) {
            float a[8], b[8];
            *(float4*)&a[0] = *(const float4*)&As[k][ty * 8];
            *(float4*)&a[4] = *(const float4*)&As[k][ty * 8 + 4];
            *(float4*)&b[0] = *(const float4*)&Bs[k][tx * 8];
            *(float4*)&b[4] = *(const float4*)&Bs[k][tx * 8 + 4];
            #pragma unroll
            for (int i = 0; i < 8; i++)
                #pragma unroll
                for (int j = 0; j < 8; j++)
                    acc[i][j] = fmaf(a[i], b[j], acc[i][j]);
        }
        __syncthreads();
    }

    #pragma unroll
    for (int i = 0; i < 8; i++) {
        int r = bm + ty * 8 + i;
        if (r >= M) continue;
        #pragma unroll
        for (int jj = 0; jj < 2; jj++) {
            int c = bn + tx * 8 + jj * 4;
            float4 o;
            o.x = acc[i][jj * 4 + 0];
            o.y = acc[i][jj * 4 + 1];
            o.z = acc[i][jj * 4 + 2];
            o.w = acc[i][jj * 4 + 3];
            if (BIAS) {
                const float4 bb = *(const float4*)&bias[c];
                o.x += bb.x; o.y += bb.y; o.z += bb.z; o.w += bb.w;
            }
            if (RELU) {
                o.x = fmaxf(o.x, 0.f); o.y = fmaxf(o.y, 0.f);
                o.z = fmaxf(o.z, 0.f); o.w = fmaxf(o.w, 0.f);
            }
            *(float4*)(C + (size_t)r * N + c) = o;
        }
    }
}

// ---------------- launch ----------------
extern "C" void kernel_launch(void* const* d_in, const int* in_sizes, int n_in,
                              void* d_out, int out_size) {
    const float* x  = (const float*)d_in[0];
    const void*  ei = d_in[1];                 // int32 or int64 — detected on device
    const float* W1 = (const float*)d_in[2];
    const float* b1 = (const float*)d_in[3];
    const float* W2 = (const float*)d_in[4];
    const float* b2 = (const float*)d_in[5];
    float*       out = (float*)d_out;

    const int E = in_sizes[1] / 2;

    float *buf128 = nullptr, *a1 = nullptr;
    cudaGetSymbolAddress((void**)&buf128, g_buf128);
    cudaGetSymbolAddress((void**)&a1, g_a1);

    // dtype sniff + CSR build (by destination) + dinv
    k_detect<<<1, 32>>>((const int*)ei);
    k_zero_cnt<<<(N_NODES + 255) / 256, 256>>>();
    k_hist<<<(E + 255) / 256, 256>>>(ei, E);
    k_part_sum<<<NPART, SCAN_B>>>();
    k_scan_part<<<1, 256>>>();
    k_fill<<<NPART, SCAN_B>>>();
    k_scatter<<<(E + 255) / 256, 256>>>(ei, E);

    const int agg_blocks = (N_NODES * 32 + 255) / 256;

    // ---- layer 1: agg1 = S x ; a1 = relu(agg1 @ W1 + b1) ----
    k_agg_csr<false><<<agg_blocks, 256>>>(x, buf128, nullptr);
    {
        dim3 grid(DIM_HID / 128, (N_NODES + 127) / 128);
        k_gemm128<true, true><<<grid, 256>>>(buf128, W1, b1, a1,
                                             N_NODES, DIM_IN, DIM_HID);
    }

    // ---- layer 2: t = a1 @ W2 ; out = S t + b2 ----
    {
        dim3 grid(DIM_OUT / 128, (N_NODES + 127) / 128);
        k_gemm128<false, false><<<grid, 256>>>(a1, W2, nullptr, buf128,
                                               N_NODES, DIM_HID, DIM_OUT);
    }
    k_agg_csr<true><<<agg_blocks, 256>>>(buf128, out, b2);
}

// round 7
// speedup vs baseline: 2.1941x; 1.7991x over previous
#include <cuda_runtime.h>
#include <cstdint>

#define N_NODES 50000
#define MAX_E   800000
#define DIM_IN  128
#define DIM_HID 256
#define DIM_OUT 128

#define SCAN_B  256
#define NPART   ((N_NODES + SCAN_B - 1) / SCAN_B)   // 196

// ---------------- scratch (static __device__, allocation-free) ----------------
__device__ int   g_is64;
__device__ int   g_cnt[N_NODES];
__device__ int   g_part[NPART];
__device__ int   g_partoff[NPART];
__device__ int   g_row[N_NODES + 1];
__device__ int   g_cursor[N_NODES];
__device__ int   g_csr_src[MAX_E];
__device__ float g_dinv[N_NODES];
__device__ float g_buf128[(size_t)N_NODES * 128];   // agg1, then t = a1 @ W2
__device__ float g_a1[(size_t)N_NODES * 256];       // relu layer-1 activations

// ---------------- edge-index dtype detection + decode ----------------
__global__ void k_detect(const int* __restrict__ ei) {
    if (threadIdx.x == 0) {
        int is64 = 1;
        for (int i = 1; i < 64; i += 2) {
            if (ei[i] != 0) { is64 = 0; break; }
        }
        g_is64 = is64;
    }
}

__device__ __forceinline__ int edge_idx(const void* __restrict__ ei, long long pos) {
    if (g_is64) return (int)((const long long*)ei)[pos];
    return ((const int*)ei)[pos];
}

// ---------------- CSR build ----------------
__global__ void k_zero_cnt() {
    int i = blockIdx.x * blockDim.x + threadIdx.x;
    if (i < N_NODES) g_cnt[i] = 0;
}

__global__ void k_hist(const void* __restrict__ ei, int E) {
    int e = blockIdx.x * blockDim.x + threadIdx.x;
    if (e >= E) return;
    int d = edge_idx(ei, (long long)E + e);
    if ((unsigned)d < N_NODES) atomicAdd(&g_cnt[d], 1);
}

__global__ void k_part_sum() {
    int i = blockIdx.x * SCAN_B + threadIdx.x;
    int c = (i < N_NODES) ? g_cnt[i] : 0;
    for (int o = 16; o > 0; o >>= 1) c += __shfl_down_sync(0xffffffff, c, o);
    __shared__ int ws[8];
    int lane = threadIdx.x & 31, wid = threadIdx.x >> 5;
    if (lane == 0) ws[wid] = c;
    __syncthreads();
    if (wid == 0) {
        int v = (lane < 8) ? ws[lane] : 0;
        for (int o = 4; o > 0; o >>= 1) v += __shfl_down_sync(0xffffffff, v, o);
        if (lane == 0) g_part[blockIdx.x] = v;
    }
}

__global__ void k_scan_part() {
    int t = threadIdx.x;
    int v = (t < NPART) ? g_part[t] : 0;
    int orig = v;
    int lane = t & 31, wid = t >> 5;
    #pragma unroll
    for (int o = 1; o < 32; o <<= 1) {
        int u = __shfl_up_sync(0xffffffff, v, o);
        if (lane >= o) v += u;
    }
    __shared__ int ws[8];
    if (lane == 31) ws[wid] = v;
    __syncthreads();
    if (wid == 0 && lane < 8) {
        int w = ws[lane];
        #pragma unroll
        for (int o = 1; o < 8; o <<= 1) {
            int u = __shfl_up_sync(0xff, w, o);
            if (lane >= o) w += u;
        }
        ws[lane] = w;
    }
    __syncthreads();
    int incl = v + (wid > 0 ? ws[wid - 1] : 0);
    if (t < NPART) g_partoff[t] = incl - orig;
}

__global__ void k_fill() {
    int b = blockIdx.x;
    int t = threadIdx.x;
    int i = b * SCAN_B + t;
    int c = (i < N_NODES) ? g_cnt[i] : 0;
    int v = c;
    int lane = t & 31, wid = t >> 5;
    #pragma unroll
    for (int o = 1; o < 32; o <<= 1) {
        int u = __shfl_up_sync(0xffffffff, v, o);
        if (lane >= o) v += u;
    }
    __shared__ int ws[8];
    if (lane == 31) ws[wid] = v;
    __syncthreads();
    if (wid == 0 && lane < 8) {
        int w = ws[lane];
        #pragma unroll
        for (int o = 1; o < 8; o <<= 1) {
            int u = __shfl_up_sync(0xff, w, o);
            if (lane >= o) w += u;
        }
        ws[lane] = w;
    }
    __syncthreads();
    int excl = v - c + (wid > 0 ? ws[wid - 1] : 0) + g_partoff[b];
    if (i < N_NODES) {
        g_row[i] = excl;
        g_cursor[i] = excl;
        g_dinv[i] = rsqrtf((float)(c + 1));
        if (i == N_NODES - 1) g_row[N_NODES] = excl + c;
    }
}

__global__ void k_scatter(const void* __restrict__ ei, int E) {
    int e = blockIdx.x * blockDim.x + threadIdx.x;
    if (e >= E) return;
    int s = edge_idx(ei, e);
    int d = edge_idx(ei, (long long)E + e);
    if ((unsigned)d >= N_NODES || (unsigned)s >= N_NODES) return;
    int pos = atomicAdd(&g_cursor[d], 1);
    g_csr_src[pos] = s;
}

// ---------------- pull aggregation ----------------
template <bool BIAS>
__global__ void k_agg_csr(const float* __restrict__ feat, float* __restrict__ out,
                          const float* __restrict__ bias) {
    int t = blockIdx.x * blockDim.x + threadIdx.x;
    int d = t >> 5;
    if (d >= N_NODES) return;
    int lane = t & 31;

    float dd = g_dinv[d];
    float4 v = ((const float4*)feat)[(size_t)d * 32 + lane];
    float sl = dd * dd;
    float4 acc;
    acc.x = v.x * sl; acc.y = v.y * sl; acc.z = v.z * sl; acc.w = v.w * sl;

    int beg = g_row[d], end = g_row[d + 1];
    for (int j = beg; j < end; j++) {
        int s = __ldg(&g_csr_src[j]);
        float norm = __ldg(&g_dinv[s]) * dd;
        float4 f = ((const float4*)feat)[(size_t)s * 32 + lane];
        acc.x = fmaf(f.x, norm, acc.x);
        acc.y = fmaf(f.y, norm, acc.y);
        acc.z = fmaf(f.z, norm, acc.z);
        acc.w = fmaf(f.w, norm, acc.w);
    }
    if (BIAS) {
        float4 b = ((const float4*)bias)[lane];
        acc.x += b.x; acc.y += b.y; acc.z += b.z; acc.w += b.w;
    }
    ((float4*)out)[(size_t)d * 32 + lane] = acc;
}

// ---------------- tf32 tensor-core GEMM ----------------
// C = A[M,K] @ B[K,N] (+bias) (+relu).  BM=128, BN=64, BK=32.
// 256 threads = 8 warps (4 m x 2 n), warp tile 32x32 = 2x4 m16n8k8 fragments.
__device__ __forceinline__ uint32_t f2tf32(float f) {
    uint32_t u;
    asm("cvt.rna.tf32.f32 %0, %1;" : "=r"(u) : "f"(f));
    return u;
}

__device__ __forceinline__ void mma_tf32(float c[4], const uint32_t a[4],
                                         const uint32_t b[2]) {
    asm volatile(
        "mma.sync.aligned.m16n8k8.row.col.f32.tf32.tf32.f32 "
        "{%0,%1,%2,%3}, {%4,%5,%6,%7}, {%8,%9}, {%0,%1,%2,%3};"
        : "+f"(c[0]), "+f"(c[1]), "+f"(c[2]), "+f"(c[3])
        : "r"(a[0]), "r"(a[1]), "r"(a[2]), "r"(a[3]), "r"(b[0]), "r"(b[1]));
}

template <bool RELU, bool BIAS>
__global__ void __launch_bounds__(256)
k_gemm_tf32(const float* __restrict__ A, const float* __restrict__ B,
            const float* __restrict__ bias, float* __restrict__ C,
            int M, int K, int N) {
    __shared__ float As[128][36];   // [m][k], pad -> bank-free frag loads
    __shared__ float Bs[32][68];    // [k][n]

    int tid  = threadIdx.x;
    int lane = tid & 31, wid = tid >> 5;
    int wm = wid & 3, wn = wid >> 2;          // 4 x 2 warps
    int gid = lane >> 2, ctg = lane & 3;
    int bm = blockIdx.y * 128, bn = blockIdx.x * 64;

    float acc[2][4][4] = {};

    for (int k0 = 0; k0 < K; k0 += 32) {
        // A tile: 128 rows x 32 k = 1024 float4-loads/4 -> 4 float4 per thread
        #pragma unroll
        for (int i = 0; i < 4; i++) {
            int idx = tid + i * 256;          // 0..1023
            int r = idx >> 3, c4 = (idx & 7) * 4;
            float4 v = make_float4(0.f, 0.f, 0.f, 0.f);
            if (bm + r < M)
                v = *(const float4*)(A + (size_t)(bm + r) * K + k0 + c4);
            float4 t;
            t.x = __uint_as_float(f2tf32(v.x));
            t.y = __uint_as_float(f2tf32(v.y));
            t.z = __uint_as_float(f2tf32(v.z));
            t.w = __uint_as_float(f2tf32(v.w));
            *(float4*)&As[r][c4] = t;
        }
        // B tile: 32 k-rows x 64 n -> 2 float4 per thread
        #pragma unroll
        for (int i = 0; i < 2; i++) {
            int idx = tid + i * 256;          // 0..511
            int r = idx >> 4, c4 = (idx & 15) * 4;
            float4 v = *(const float4*)(B + (size_t)(k0 + r) * N + bn + c4);
            float4 t;
            t.x = __uint_as_float(f2tf32(v.x));
            t.y = __uint_as_float(f2tf32(v.y));
            t.z = __uint_as_float(f2tf32(v.z));
            t.w = __uint_as_float(f2tf32(v.w));
            *(float4*)&Bs[r][c4] = t;
        }
        __syncthreads();

        #pragma unroll
        for (int ks = 0; ks < 4; ks++) {
            int kk = ks * 8;
            uint32_t a[2][4], b[4][2];
            #pragma unroll
            for (int mi = 0; mi < 2; mi++) {
                int m0 = wm * 32 + mi * 16 + gid;
                a[mi][0] = __float_as_uint(As[m0][kk + ctg]);
                a[mi][1] = __float_as_uint(As[m0 + 8][kk + ctg]);
                a[mi][2] = __float_as_uint(As[m0][kk + ctg + 4]);
                a[mi][3] = __float_as_uint(As[m0 + 8][kk + ctg + 4]);
            }
            #pragma unroll
            for (int ni = 0; ni < 4; ni++) {
                int n0 = wn * 32 + ni * 8 + gid;
                b[ni][0] = __float_as_uint(Bs[kk + ctg][n0]);
                b[ni][1] = __float_as_uint(Bs[kk + ctg + 4][n0]);
            }
            #pragma unroll
            for (int mi = 0; mi < 2; mi++)
                #pragma unroll
                for (int ni = 0; ni < 4; ni++)
                    mma_tf32(acc[mi][ni], a[mi], b[ni]);
        }
        __syncthreads();
    }

    // epilogue: c0,c1 -> (row, col..col+1); c2,c3 -> (row+8, ...)
    #pragma unroll
    for (int mi = 0; mi < 2; mi++) {
        #pragma unroll
        for (int ni = 0; ni < 4; ni++) {
            int r0 = bm + wm * 32 + mi * 16 + gid;
            int c  = bn + wn * 32 + ni * 8 + ctg * 2;
            float2 v0 = make_float2(acc[mi][ni][0], acc[mi][ni][1]);
            float2 v1 = make_float2(acc[mi][ni][2], acc[mi][ni][3]);
            if (BIAS) {
                float2 bb = *(const float2*)&bias[c];
                v0.x += bb.x; v0.y += bb.y;
                v1.x += bb.x; v1.y += bb.y;
            }
            if (RELU) {
                v0.x = fmaxf(v0.x, 0.f); v0.y = fmaxf(v0.y, 0.f);
                v1.x = fmaxf(v1.x, 0.f); v1.y = fmaxf(v1.y, 0.f);
            }
            if (r0 < M)     *(float2*)(C + (size_t)r0 * N + c) = v0;
            if (r0 + 8 < M) *(float2*)(C + (size_t)(r0 + 8) * N + c) = v1;
        }
    }
}

// ---------------- launch ----------------
extern "C" void kernel_launch(void* const* d_in, const int* in_sizes, int n_in,
                              void* d_out, int out_size) {
    const float* x  = (const float*)d_in[0];
    const void*  ei = d_in[1];
    const float* W1 = (const float*)d_in[2];
    const float* b1 = (const float*)d_in[3];
    const float* W2 = (const float*)d_in[4];
    const float* b2 = (const float*)d_in[5];
    float*       out = (float*)d_out;

    const int E = in_sizes[1] / 2;

    float *buf128 = nullptr, *a1 = nullptr;
    cudaGetSymbolAddress((void**)&buf128, g_buf128);
    cudaGetSymbolAddress((void**)&a1, g_a1);

    k_detect<<<1, 32>>>((const int*)ei);
    k_zero_cnt<<<(N_NODES + 255) / 256, 256>>>();
    k_hist<<<(E + 255) / 256, 256>>>(ei, E);
    k_part_sum<<<NPART, SCAN_B>>>();
    k_scan_part<<<1, 256>>>();
    k_fill<<<NPART, SCAN_B>>>();
    k_scatter<<<(E + 255) / 256, 256>>>(ei, E);

    const int agg_blocks = (N_NODES * 32 + 255) / 256;

    // ---- layer 1: agg1 = S x ; a1 = relu(agg1 @ W1 + b1) ----
    k_agg_csr<false><<<agg_blocks, 256>>>(x, buf128, nullptr);
    {
        dim3 grid(DIM_HID / 64, (N_NODES + 127) / 128);
        k_gemm_tf32<true, true><<<grid, 256>>>(buf128, W1, b1, a1,
                                               N_NODES, DIM_IN, DIM_HID);
    }

    // ---- layer 2: t = a1 @ W2 ; out = S t + b2 ----
    {
        dim3 grid(DIM_OUT / 64, (N_NODES + 127) / 128);
        k_gemm_tf32<false, false><<<grid, 256>>>(a1, W2, nullptr, buf128,
                                                 N_NODES, DIM_HID, DIM_OUT);
    }
    k_agg_csr<true><<<agg_blocks, 256>>>(buf128, out, b2);
}

// round 8
// speedup vs baseline: 2.2091x; 1.0068x over previous
#include <cuda_runtime.h>
#include <cuda_fp16.h>
#include <cstdint>

#define N_NODES 50000
#define MAX_E   800000
#define DIM_IN  128
#define DIM_HID 256
#define DIM_OUT 128

#define SCAN_B  256
#define NPART   ((N_NODES + SCAN_B - 1) / SCAN_B)   // 196

// ---------------- scratch (static __device__, allocation-free) ----------------
__device__ int    g_is64;
__device__ int    g_cnt[N_NODES];
__device__ int    g_part[NPART];
__device__ int    g_partoff[NPART];
__device__ int    g_row[N_NODES + 1];
__device__ int    g_cursor[N_NODES];
__device__ int    g_csr_src[MAX_E];
__device__ int    g_src32[MAX_E];
__device__ int    g_dst32[MAX_E];
__device__ float  g_dinv[N_NODES];
__device__ float  g_buf128[(size_t)N_NODES * 128];  // agg1 (fp32)
__device__ float  g_a1[(size_t)N_NODES * 256];      // relu layer-1 activations
__device__ __half g_xh[(size_t)N_NODES * 128];      // x in half
__device__ __half g_th[(size_t)N_NODES * 128];      // t = a1@W2 in half

// ---------------- edge-index dtype detection + decode ----------------
__global__ void k_detect(const int* __restrict__ ei) {
    if (threadIdx.x == 0) {
        int is64 = 1;
        for (int i = 1; i < 64; i += 2) {
            if (ei[i] != 0) { is64 = 0; break; }
        }
        g_is64 = is64;
    }
}

__device__ __forceinline__ int edge_idx(const void* __restrict__ ei, long long pos) {
    if (g_is64) return (int)((const long long*)ei)[pos];
    return ((const int*)ei)[pos];
}

// ---------------- CSR build ----------------
__global__ void k_zero_cnt() {
    int i = blockIdx.x * blockDim.x + threadIdx.x;
    if (i < N_NODES) g_cnt[i] = 0;
}

// hist + int32 staging of the edge list
__global__ void k_hist(const void* __restrict__ ei, int E) {
    int e = blockIdx.x * blockDim.x + threadIdx.x;
    if (e >= E) return;
    int s = edge_idx(ei, e);
    int d = edge_idx(ei, (long long)E + e);
    g_src32[e] = s;
    g_dst32[e] = d;
    if ((unsigned)d < N_NODES) atomicAdd(&g_cnt[d], 1);
}

__global__ void k_part_sum() {
    int i = blockIdx.x * SCAN_B + threadIdx.x;
    int c = (i < N_NODES) ? g_cnt[i] : 0;
    for (int o = 16; o > 0; o >>= 1) c += __shfl_down_sync(0xffffffff, c, o);
    __shared__ int ws[8];
    int lane = threadIdx.x & 31, wid = threadIdx.x >> 5;
    if (lane == 0) ws[wid] = c;
    __syncthreads();
    if (wid == 0) {
        int v = (lane < 8) ? ws[lane] : 0;
        for (int o = 4; o > 0; o >>= 1) v += __shfl_down_sync(0xffffffff, v, o);
        if (lane == 0) g_part[blockIdx.x] = v;
    }
}

__global__ void k_scan_part() {
    int t = threadIdx.x;
    int v = (t < NPART) ? g_part[t] : 0;
    int orig = v;
    int lane = t & 31, wid = t >> 5;
    #pragma unroll
    for (int o = 1; o < 32; o <<= 1) {
        int u = __shfl_up_sync(0xffffffff, v, o);
        if (lane >= o) v += u;
    }
    __shared__ int ws[8];
    if (lane == 31) ws[wid] = v;
    __syncthreads();
    if (wid == 0 && lane < 8) {
        int w = ws[lane];
        #pragma unroll
        for (int o = 1; o < 8; o <<= 1) {
            int u = __shfl_up_sync(0xff, w, o);
            if (lane >= o) w += u;
        }
        ws[lane] = w;
    }
    __syncthreads();
    int incl = v + (wid > 0 ? ws[wid - 1] : 0);
    if (t < NPART) g_partoff[t] = incl - orig;
}

__global__ void k_fill() {
    int b = blockIdx.x;
    int t = threadIdx.x;
    int i = b * SCAN_B + t;
    int c = (i < N_NODES) ? g_cnt[i] : 0;
    int v = c;
    int lane = t & 31, wid = t >> 5;
    #pragma unroll
    for (int o = 1; o < 32; o <<= 1) {
        int u = __shfl_up_sync(0xffffffff, v, o);
        if (lane >= o) v += u;
    }
    __shared__ int ws[8];
    if (lane == 31) ws[wid] = v;
    __syncthreads();
    if (wid == 0 && lane < 8) {
        int w = ws[lane];
        #pragma unroll
        for (int o = 1; o < 8; o <<= 1) {
            int u = __shfl_up_sync(0xff, w, o);
            if (lane >= o) w += u;
        }
        ws[lane] = w;
    }
    __syncthreads();
    int excl = v - c + (wid > 0 ? ws[wid - 1] : 0) + g_partoff[b];
    if (i < N_NODES) {
        g_row[i] = excl;
        g_cursor[i] = excl;
        g_dinv[i] = rsqrtf((float)(c + 1));
        if (i == N_NODES - 1) g_row[N_NODES] = excl + c;
    }
}

__global__ void k_scatter(int E) {
    int e = blockIdx.x * blockDim.x + threadIdx.x;
    if (e >= E) return;
    int s = g_src32[e];
    int d = g_dst32[e];
    if ((unsigned)d >= N_NODES || (unsigned)s >= N_NODES) return;
    int pos = atomicAdd(&g_cursor[d], 1);
    g_csr_src[pos] = s;
}

// ---------------- fp32 -> half conversion (feature matrix) ----------------
__global__ void k_f2h(const float* __restrict__ in, __half* __restrict__ out) {
    int i = blockIdx.x * blockDim.x + threadIdx.x;      // one float4 per thread
    if (i >= N_NODES * 32) return;
    float4 v = ((const float4*)in)[i];
    __half2 h0 = __floats2half2_rn(v.x, v.y);
    __half2 h1 = __floats2half2_rn(v.z, v.w);
    uint2 o;
    o.x = *(uint32_t*)&h0;
    o.y = *(uint32_t*)&h1;
    ((uint2*)out)[i] = o;
}

// ---------------- pull aggregation (half features, fp32 accumulate) ----------
// out[d] = sum_{s in N(d)} feat[s]*dinv[s]*dinv[d] + feat[d]*dinv[d]^2 (+bias)
// One warp per node, one uint2 (4 halves) per lane = 128 features.
template <bool BIAS>
__global__ void k_agg_h(const __half* __restrict__ feat, float* __restrict__ out,
                        const float* __restrict__ bias) {
    int t = blockIdx.x * blockDim.x + threadIdx.x;
    int d = t >> 5;
    if (d >= N_NODES) return;
    int lane = t & 31;

    float dd = g_dinv[d];
    float sl = dd * dd;

    uint2 sv = ((const uint2*)feat)[(size_t)d * 32 + lane];
    float2 f0 = __half22float2(*(__half2*)&sv.x);
    float2 f1 = __half22float2(*(__half2*)&sv.y);
    float4 acc;
    acc.x = f0.x * sl; acc.y = f0.y * sl; acc.z = f1.x * sl; acc.w = f1.y * sl;

    int beg = g_row[d], end = g_row[d + 1];
    for (int j = beg; j < end; j++) {
        int s = __ldg(&g_csr_src[j]);
        float norm = __ldg(&g_dinv[s]) * dd;
        uint2 v = ((const uint2*)feat)[(size_t)s * 32 + lane];
        float2 a = __half22float2(*(__half2*)&v.x);
        float2 b = __half22float2(*(__half2*)&v.y);
        acc.x = fmaf(a.x, norm, acc.x);
        acc.y = fmaf(a.y, norm, acc.y);
        acc.z = fmaf(b.x, norm, acc.z);
        acc.w = fmaf(b.y, norm, acc.w);
    }
    if (BIAS) {
        float4 b = ((const float4*)bias)[lane];
        acc.x += b.x; acc.y += b.y; acc.z += b.z; acc.w += b.w;
    }
    ((float4*)out)[(size_t)d * 32 + lane] = acc;
}

// ---------------- tf32 tensor-core GEMM ----------------
// C = A[M,K] @ B[K,N] (+bias) (+relu).  BM=128, BN=64, BK=32.
// 256 threads = 8 warps (4 m x 2 n), warp tile 32x32 = 2x4 m16n8k8 fragments.
// HALF_OUT: write __half output (for feeding the aggregation) instead of fp32.
__device__ __forceinline__ uint32_t f2tf32(float f) {
    uint32_t u;
    asm("cvt.rna.tf32.f32 %0, %1;" : "=r"(u) : "f"(f));
    return u;
}

__device__ __forceinline__ void mma_tf32(float c[4], const uint32_t a[4],
                                         const uint32_t b[2]) {
    asm volatile(
        "mma.sync.aligned.m16n8k8.row.col.f32.tf32.tf32.f32 "
        "{%0,%1,%2,%3}, {%4,%5,%6,%7}, {%8,%9}, {%0,%1,%2,%3};"
        : "+f"(c[0]), "+f"(c[1]), "+f"(c[2]), "+f"(c[3])
        : "r"(a[0]), "r"(a[1]), "r"(a[2]), "r"(a[3]), "r"(b[0]), "r"(b[1]));
}

template <bool RELU, bool BIAS, bool HALF_OUT>
__global__ void __launch_bounds__(256)
k_gemm_tf32(const float* __restrict__ A, const float* __restrict__ B,
            const float* __restrict__ bias, float* __restrict__ C,
            __half* __restrict__ Ch, int M, int K, int N) {
    __shared__ float As[128][36];
    __shared__ float Bs[32][68];

    int tid  = threadIdx.x;
    int lane = tid & 31, wid = tid >> 5;
    int wm = wid & 3, wn = wid >> 2;          // 4 x 2 warps
    int gid = lane >> 2, ctg = lane & 3;
    int bm = blockIdx.y * 128, bn = blockIdx.x * 64;

    float acc[2][4][4] = {};

    for (int k0 = 0; k0 < K; k0 += 32) {
        #pragma unroll
        for (int i = 0; i < 4; i++) {
            int idx = tid + i * 256;
            int r = idx >> 3, c4 = (idx & 7) * 4;
            float4 v = make_float4(0.f, 0.f, 0.f, 0.f);
            if (bm + r < M)
                v = *(const float4*)(A + (size_t)(bm + r) * K + k0 + c4);
            float4 t;
            t.x = __uint_as_float(f2tf32(v.x));
            t.y = __uint_as_float(f2tf32(v.y));
            t.z = __uint_as_float(f2tf32(v.z));
            t.w = __uint_as_float(f2tf32(v.w));
            *(float4*)&As[r][c4] = t;
        }
        #pragma unroll
        for (int i = 0; i < 2; i++) {
            int idx = tid + i * 256;
            int r = idx >> 4, c4 = (idx & 15) * 4;
            float4 v = *(const float4*)(B + (size_t)(k0 + r) * N + bn + c4);
            float4 t;
            t.x = __uint_as_float(f2tf32(v.x));
            t.y = __uint_as_float(f2tf32(v.y));
            t.z = __uint_as_float(f2tf32(v.z));
            t.w = __uint_as_float(f2tf32(v.w));
            *(float4*)&Bs[r][c4] = t;
        }
        __syncthreads();

        #pragma unroll
        for (int ks = 0; ks < 4; ks++) {
            int kk = ks * 8;
            uint32_t a[2][4], b[4][2];
            #pragma unroll
            for (int mi = 0; mi < 2; mi++) {
                int m0 = wm * 32 + mi * 16 + gid;
                a[mi][0] = __float_as_uint(As[m0][kk + ctg]);
                a[mi][1] = __float_as_uint(As[m0 + 8][kk + ctg]);
                a[mi][2] = __float_as_uint(As[m0][kk + ctg + 4]);
                a[mi][3] = __float_as_uint(As[m0 + 8][kk + ctg + 4]);
            }
            #pragma unroll
            for (int ni = 0; ni < 4; ni++) {
                int n0 = wn * 32 + ni * 8 + gid;
                b[ni][0] = __float_as_uint(Bs[kk + ctg][n0]);
                b[ni][1] = __float_as_uint(Bs[kk + ctg + 4][n0]);
            }
            #pragma unroll
            for (int mi = 0; mi < 2; mi++)
                #pragma unroll
                for (int ni = 0; ni < 4; ni++)
                    mma_tf32(acc[mi][ni], a[mi], b[ni]);
        }
        __syncthreads();
    }

    #pragma unroll
    for (int mi = 0; mi < 2; mi++) {
        #pragma unroll
        for (int ni = 0; ni < 4; ni++) {
            int r0 = bm + wm * 32 + mi * 16 + gid;
            int c  = bn + wn * 32 + ni * 8 + ctg * 2;
            float2 v0 = make_float2(acc[mi][ni][0], acc[mi][ni][1]);
            float2 v1 = make_float2(acc[mi][ni][2], acc[mi][ni][3]);
            if (BIAS) {
                float2 bb = *(const float2*)&bias[c];
                v0.x += bb.x; v0.y += bb.y;
                v1.x += bb.x; v1.y += bb.y;
            }
            if (RELU) {
                v0.x = fmaxf(v0.x, 0.f); v0.y = fmaxf(v0.y, 0.f);
                v1.x = fmaxf(v1.x, 0.f); v1.y = fmaxf(v1.y, 0.f);
            }
            if (HALF_OUT) {
                __half2 h0 = __floats2half2_rn(v0.x, v0.y);
                __half2 h1 = __floats2half2_rn(v1.x, v1.y);
                if (r0 < M)     *(__half2*)(Ch + (size_t)r0 * N + c) = h0;
                if (r0 + 8 < M) *(__half2*)(Ch + (size_t)(r0 + 8) * N + c) = h1;
            } else {
                if (r0 < M)     *(float2*)(C + (size_t)r0 * N + c) = v0;
                if (r0 + 8 < M) *(float2*)(C + (size_t)(r0 + 8) * N + c) = v1;
            }
        }
    }
}

// ---------------- launch ----------------
extern "C" void kernel_launch(void* const* d_in, const int* in_sizes, int n_in,
                              void* d_out, int out_size) {
    const float* x  = (const float*)d_in[0];
    const void*  ei = d_in[1];
    const float* W1 = (const float*)d_in[2];
    const float* b1 = (const float*)d_in[3];
    const float* W2 = (const float*)d_in[4];
    const float* b2 = (const float*)d_in[5];
    float*       out = (float*)d_out;

    const int E = in_sizes[1] / 2;

    float *buf128 = nullptr, *a1 = nullptr;
    __half *xh = nullptr, *th = nullptr;
    cudaGetSymbolAddress((void**)&buf128, g_buf128);
    cudaGetSymbolAddress((void**)&a1, g_a1);
    cudaGetSymbolAddress((void**)&xh, g_xh);
    cudaGetSymbolAddress((void**)&th, g_th);

    k_detect<<<1, 32>>>((const int*)ei);
    k_zero_cnt<<<(N_NODES + 255) / 256, 256>>>();
    k_hist<<<(E + 255) / 256, 256>>>(ei, E);
    k_part_sum<<<NPART, SCAN_B>>>();
    k_scan_part<<<1, 256>>>();
    k_fill<<<NPART, SCAN_B>>>();
    k_scatter<<<(E + 255) / 256, 256>>>(E);

    const int cvt_blocks = (N_NODES * 32 + 255) / 256;
    const int agg_blocks = (N_NODES * 32 + 255) / 256;

    // ---- layer 1: agg1 = S x (half gather) ; a1 = relu(agg1 @ W1 + b1) ----
    k_f2h<<<cvt_blocks, 256>>>(x, xh);
    k_agg_h<false><<<agg_blocks, 256>>>(xh, buf128, nullptr);
    {
        dim3 grid(DIM_HID / 64, (N_NODES + 127) / 128);
        k_gemm_tf32<true, true, false><<<grid, 256>>>(buf128, W1, b1, a1, nullptr,
                                                      N_NODES, DIM_IN, DIM_HID);
    }

    // ---- layer 2: t = a1 @ W2 (half out) ; out = S t + b2 ----
    {
        dim3 grid(DIM_OUT / 64, (N_NODES + 127) / 128);
        k_gemm_tf32<false, false, true><<<grid, 256>>>(a1, W2, nullptr, nullptr, th,
                                                       N_NODES, DIM_HID, DIM_OUT);
    }
    k_agg_h<true><<<agg_blocks, 256>>>(th, out, b2);
}

// round 10
// speedup vs baseline: 2.3579x; 1.0674x over previous
#include <cuda_runtime.h>
#include <cuda_fp16.h>
#include <cstdint>

#define N_NODES 50000
#define MAX_E   800000
#define DIM_IN  128
#define DIM_HID 256
#define DIM_OUT 128

#define SCAN_B  256
#define NPART   ((N_NODES + SCAN_B - 1) / SCAN_B)   // 196

// ---------------- scratch (static __device__, allocation-free) ----------------
__device__ int    g_is64;
__device__ int    g_base;
__device__ int    g_cnt[N_NODES];
__device__ int    g_row[N_NODES];
__device__ int    g_cursor[N_NODES];
__device__ int    g_csr_src[MAX_E];
__device__ float  g_w[MAX_E];
__device__ int    g_src32[MAX_E];
__device__ int    g_dst32[MAX_E];
__device__ float  g_dinv[N_NODES];
__device__ float  g_buf128[(size_t)N_NODES * 128];  // agg1 (fp32)
__device__ float  g_a1[(size_t)N_NODES * 256];      // relu layer-1 activations
__device__ __half g_xh[(size_t)N_NODES * 128];      // x in half
__device__ __half g_th[(size_t)N_NODES * 128];      // t = a1@W2 in half

// ---------------- helpers ----------------
__device__ __forceinline__ int edge_idx(const void* __restrict__ ei, long long pos) {
    if (g_is64) return (int)((const long long*)ei)[pos];
    return ((const int*)ei)[pos];
}

__device__ __forceinline__ uint32_t smem_u32(const void* p) {
    return (uint32_t)__cvta_generic_to_shared(p);
}
__device__ __forceinline__ void cp16(uint32_t dst, const void* src, bool pred) {
    int sz = pred ? 16 : 0;
    asm volatile("cp.async.ca.shared.global [%0], [%1], 16, %2;"
                 :: "r"(dst), "l"(src), "r"(sz));
}

// ---------------- init: zero counters, reset base, sniff dtype ----------------
__global__ void k_init(const int* __restrict__ ei) {
    int i = blockIdx.x * blockDim.x + threadIdx.x;
    if (i < N_NODES) g_cnt[i] = 0;
    if (i == 0) {
        g_base = 0;
        int is64 = 1;
        for (int k = 1; k < 64; k += 2)
            if (ei[k] != 0) { is64 = 0; break; }
        g_is64 = is64;
    }
}

// ---------------- hist + int32 staging + x->half conversion (fused) -----------
__global__ void k_hist_f2h(const void* __restrict__ ei, const float* __restrict__ x,
                           int E) {
    int i = blockIdx.x * blockDim.x + threadIdx.x;
    if (i < E) {
        int s = edge_idx(ei, i);
        int d = edge_idx(ei, (long long)E + i);
        g_src32[i] = s;
        g_dst32[i] = d;
        if ((unsigned)s < N_NODES && (unsigned)d < N_NODES)
            atomicAdd(&g_cnt[d], 1);
    }
    if (i < N_NODES * 32) {
        float4 v = ((const float4*)x)[i];
        __half2 h0 = __floats2half2_rn(v.x, v.y);
        __half2 h1 = __floats2half2_rn(v.z, v.w);
        uint2 o;
        o.x = *(uint32_t*)&h0;
        o.y = *(uint32_t*)&h1;
        ((uint2*)g_xh)[i] = o;
    }
}

// ---------------- single-kernel scan+fill (atomic block base) -----------------
// CSR segments need only be disjoint, not node-ordered.
__global__ void k_scanfill() {
    int b = blockIdx.x, t = threadIdx.x;
    int i = b * SCAN_B + t;
    int c = (i < N_NODES) ? g_cnt[i] : 0;
    int lane = t & 31, wid = t >> 5;
    int v = c;
    #pragma unroll
    for (int o = 1; o < 32; o <<= 1) {
        int u = __shfl_up_sync(0xffffffff, v, o);
        if (lane >= o) v += u;
    }
    __shared__ int ws[8];
    __shared__ int sbase;
    if (lane == 31) ws[wid] = v;
    __syncthreads();
    if (wid == 0 && lane < 8) {
        int w = ws[lane];
        #pragma unroll
        for (int o = 1; o < 8; o <<= 1) {
            int u = __shfl_up_sync(0xff, w, o);
            if (lane >= o) w += u;
        }
        ws[lane] = w;
    }
    __syncthreads();
    if (t == 0) sbase = atomicAdd(&g_base, ws[7]);
    __syncthreads();
    int excl = v - c + (wid > 0 ? ws[wid - 1] : 0) + sbase;
    if (i < N_NODES) {
        g_row[i] = excl;
        g_cursor[i] = excl;
        g_dinv[i] = rsqrtf((float)(c + 1));   // +1 self-loop
    }
}

// ---------------- scatter: fill CSR (src, precomputed weight) -----------------
__global__ void k_scatter(int E) {
    int e = blockIdx.x * blockDim.x + threadIdx.x;
    if (e >= E) return;
    int s = g_src32[e];
    int d = g_dst32[e];
    if ((unsigned)d >= N_NODES || (unsigned)s >= N_NODES) return;
    int pos = atomicAdd(&g_cursor[d], 1);
    g_csr_src[pos] = s;
    g_w[pos] = g_dinv[s] * g_dinv[d];
}

// ---------------- pull aggregation (half feats, fp32 acc, unroll x4) ----------
template <bool BIAS>
__global__ void k_agg_h(const __half* __restrict__ feat, float* __restrict__ out,
                        const float* __restrict__ bias) {
    int t = blockIdx.x * blockDim.x + threadIdx.x;
    int d = t >> 5;
    if (d >= N_NODES) return;
    int lane = t & 31;

    const uint2* f2 = (const uint2*)feat;
    float dd = g_dinv[d];
    float sl = dd * dd;

    uint2 sv = __ldg(&f2[(size_t)d * 32 + lane]);
    float2 a0 = __half22float2(*(__half2*)&sv.x);
    float2 a1 = __half22float2(*(__half2*)&sv.y);
    float4 acc;
    acc.x = a0.x * sl; acc.y = a0.y * sl; acc.z = a1.x * sl; acc.w = a1.y * sl;

    int beg = g_row[d];
    int end = beg + g_cnt[d];
    int j = beg;
    for (; j + 4 <= end; j += 4) {
        int s0 = __ldg(&g_csr_src[j + 0]);
        int s1 = __ldg(&g_csr_src[j + 1]);
        int s2 = __ldg(&g_csr_src[j + 2]);
        int s3 = __ldg(&g_csr_src[j + 3]);
        float w0 = __ldg(&g_w[j + 0]);
        float w1 = __ldg(&g_w[j + 1]);
        float w2 = __ldg(&g_w[j + 2]);
        float w3 = __ldg(&g_w[j + 3]);
        uint2 v0 = __ldg(&f2[(size_t)s0 * 32 + lane]);
        uint2 v1 = __ldg(&f2[(size_t)s1 * 32 + lane]);
        uint2 v2 = __ldg(&f2[(size_t)s2 * 32 + lane]);
        uint2 v3 = __ldg(&f2[(size_t)s3 * 32 + lane]);
        {
            float2 x0 = __half22float2(*(__half2*)&v0.x);
            float2 x1 = __half22float2(*(__half2*)&v0.y);
            acc.x = fmaf(x0.x, w0, acc.x); acc.y = fmaf(x0.y, w0, acc.y);
            acc.z = fmaf(x1.x, w0, acc.z); acc.w = fmaf(x1.y, w0, acc.w);
        }
        {
            float2 x0 = __half22float2(*(__half2*)&v1.x);
            float2 x1 = __half22float2(*(__half2*)&v1.y);
            acc.x = fmaf(x0.x, w1, acc.x); acc.y = fmaf(x0.y, w1, acc.y);
            acc.z = fmaf(x1.x, w1, acc.z); acc.w = fmaf(x1.y, w1, acc.w);
        }
        {
            float2 x0 = __half22float2(*(__half2*)&v2.x);
            float2 x1 = __half22float2(*(__half2*)&v2.y);
            acc.x = fmaf(x0.x, w2, acc.x); acc.y = fmaf(x0.y, w2, acc.y);
            acc.z = fmaf(x1.x, w2, acc.z); acc.w = fmaf(x1.y, w2, acc.w);
        }
        {
            float2 x0 = __half22float2(*(__half2*)&v3.x);
            float2 x1 = __half22float2(*(__half2*)&v3.y);
            acc.x = fmaf(x0.x, w3, acc.x); acc.y = fmaf(x0.y, w3, acc.y);
            acc.z = fmaf(x1.x, w3, acc.z); acc.w = fmaf(x1.y, w3, acc.w);
        }
    }
    for (; j < end; j++) {
        int s = __ldg(&g_csr_src[j]);
        float w = __ldg(&g_w[j]);
        uint2 v = __ldg(&f2[(size_t)s * 32 + lane]);
        float2 x0 = __half22float2(*(__half2*)&v.x);
        float2 x1 = __half22float2(*(__half2*)&v.y);
        acc.x = fmaf(x0.x, w, acc.x); acc.y = fmaf(x0.y, w, acc.y);
        acc.z = fmaf(x1.x, w, acc.z); acc.w = fmaf(x1.y, w, acc.w);
    }
    if (BIAS) {
        float4 b = ((const float4*)bias)[lane];
        acc.x += b.x; acc.y += b.y; acc.z += b.z; acc.w += b.w;
    }
    ((float4*)out)[(size_t)d * 32 + lane] = acc;
}

// ---------------- tf32 tensor-core GEMM (cp.async double-buffered) ------------
// C = A[M,K] @ B[K,N] (+bias) (+relu).  BM=128, BN=64, BK=32, 2 stages.
// 256 threads = 8 warps (4 m x 2 n), warp tile 32x32 = 2x4 m16n8k8 fragments.
// Fragments are rounded to tf32 with cvt.rna in registers (R9 truncation
// failed accuracy: 1.41e-3 > 1e-3).
#define GEMM_SMEM ((2 * 128 * 36 + 2 * 32 * 68) * 4)

__device__ __forceinline__ uint32_t f2tf32(float f) {
    uint32_t u;
    asm("cvt.rna.tf32.f32 %0, %1;" : "=r"(u) : "f"(f));
    return u;
}

__device__ __forceinline__ void mma_tf32(float c[4], const uint32_t a[4],
                                         const uint32_t b[2]) {
    asm volatile(
        "mma.sync.aligned.m16n8k8.row.col.f32.tf32.tf32.f32 "
        "{%0,%1,%2,%3}, {%4,%5,%6,%7}, {%8,%9}, {%0,%1,%2,%3};"
        : "+f"(c[0]), "+f"(c[1]), "+f"(c[2]), "+f"(c[3])
        : "r"(a[0]), "r"(a[1]), "r"(a[2]), "r"(a[3]), "r"(b[0]), "r"(b[1]));
}

template <bool RELU, bool BIAS, bool HALF_OUT>
__global__ void __launch_bounds__(256)
k_gemm_tf32(const float* __restrict__ A, const float* __restrict__ B,
            const float* __restrict__ bias, float* __restrict__ C,
            __half* __restrict__ Ch, int M, int K, int N) {
    extern __shared__ float smem[];
    float (*As)[128][36] = (float(*)[128][36])smem;
    float (*Bs)[32][68]  = (float(*)[32][68])(smem + 2 * 128 * 36);

    int tid  = threadIdx.x;
    int lane = tid & 31, wid = tid >> 5;
    int wm = wid & 3, wn = wid >> 2;          // 4 x 2 warps
    int gid = lane >> 2, ctg = lane & 3;
    int bm = blockIdx.y * 128, bn = blockIdx.x * 64;

    const int NT = K / 32;

    auto issue_tile = [&](int kt, int stage) {
        int k0 = kt * 32;
        #pragma unroll
        for (int i = 0; i < 4; i++) {
            int idx = tid + i * 256;
            int r = idx >> 3, c4 = (idx & 7) * 4;
            bool ok = (bm + r) < M;
            cp16(smem_u32(&As[stage][r][c4]),
                 A + (size_t)(bm + r) * K + k0 + c4, ok);
        }
        #pragma unroll
        for (int i = 0; i < 2; i++) {
            int idx = tid + i * 256;
            int r = idx >> 4, c4 = (idx & 15) * 4;
            cp16(smem_u32(&Bs[stage][r][c4]),
                 B + (size_t)(k0 + r) * N + bn + c4, true);
        }
        asm volatile("cp.async.commit_group;");
    };

    float acc[2][4][4] = {};

    issue_tile(0, 0);
    for (int kt = 0; kt < NT; kt++) {
        int cur = kt & 1;
        if (kt + 1 < NT) {
            issue_tile(kt + 1, cur ^ 1);
            asm volatile("cp.async.wait_group 1;");
        } else {
            asm volatile("cp.async.wait_group 0;");
        }
        __syncthreads();

        #pragma unroll
        for (int ks = 0; ks < 4; ks++) {
            int kk = ks * 8;
            uint32_t a[2][4], b[4][2];
            #pragma unroll
            for (int mi = 0; mi < 2; mi++) {
                int m0 = wm * 32 + mi * 16 + gid;
                a[mi][0] = f2tf32(As[cur][m0][kk + ctg]);
                a[mi][1] = f2tf32(As[cur][m0 + 8][kk + ctg]);
                a[mi][2] = f2tf32(As[cur][m0][kk + ctg + 4]);
                a[mi][3] = f2tf32(As[cur][m0 + 8][kk + ctg + 4]);
            }
            #pragma unroll
            for (int ni = 0; ni < 4; ni++) {
                int n0 = wn * 32 + ni * 8 + gid;
                b[ni][0] = f2tf32(Bs[cur][kk + ctg][n0]);
                b[ni][1] = f2tf32(Bs[cur][kk + ctg + 4][n0]);
            }
            #pragma unroll
            for (int mi = 0; mi < 2; mi++)
                #pragma unroll
                for (int ni = 0; ni < 4; ni++)
                    mma_tf32(acc[mi][ni], a[mi], b[ni]);
        }
        __syncthreads();
    }

    #pragma unroll
    for (int mi = 0; mi < 2; mi++) {
        #pragma unroll
        for (int ni = 0; ni < 4; ni++) {
            int r0 = bm + wm * 32 + mi * 16 + gid;
            int c  = bn + wn * 32 + ni * 8 + ctg * 2;
            float2 v0 = make_float2(acc[mi][ni][0], acc[mi][ni][1]);
            float2 v1 = make_float2(acc[mi][ni][2], acc[mi][ni][3]);
            if (BIAS) {
                float2 bb = *(const float2*)&bias[c];
                v0.x += bb.x; v0.y += bb.y;
                v1.x += bb.x; v1.y += bb.y;
            }
            if (RELU) {
                v0.x = fmaxf(v0.x, 0.f); v0.y = fmaxf(v0.y, 0.f);
                v1.x = fmaxf(v1.x, 0.f); v1.y = fmaxf(v1.y, 0.f);
            }
            if (HALF_OUT) {
                __half2 h0 = __floats2half2_rn(v0.x, v0.y);
                __half2 h1 = __floats2half2_rn(v1.x, v1.y);
                if (r0 < M)     *(__half2*)(Ch + (size_t)r0 * N + c) = h0;
                if (r0 + 8 < M) *(__half2*)(Ch + (size_t)(r0 + 8) * N + c) = h1;
            } else {
                if (r0 < M)     *(float2*)(C + (size_t)r0 * N + c) = v0;
                if (r0 + 8 < M) *(float2*)(C + (size_t)(r0 + 8) * N + c) = v1;
            }
        }
    }
}

// ---------------- launch ----------------
extern "C" void kernel_launch(void* const* d_in, const int* in_sizes, int n_in,
                              void* d_out, int out_size) {
    const float* x  = (const float*)d_in[0];
    const void*  ei = d_in[1];
    const float* W1 = (const float*)d_in[2];
    const float* b1 = (const float*)d_in[3];
    const float* W2 = (const float*)d_in[4];
    const float* b2 = (const float*)d_in[5];
    float*       out = (float*)d_out;

    const int E = in_sizes[1] / 2;

    float *buf128 = nullptr, *a1 = nullptr;
    __half *xh = nullptr, *th = nullptr;
    cudaGetSymbolAddress((void**)&buf128, g_buf128);
    cudaGetSymbolAddress((void**)&a1, g_a1);
    cudaGetSymbolAddress((void**)&xh, g_xh);
    cudaGetSymbolAddress((void**)&th, g_th);

    static bool attr_done = false;
    if (!attr_done) {
        cudaFuncSetAttribute(k_gemm_tf32<true, true, false>,
                             cudaFuncAttributeMaxDynamicSharedMemorySize, GEMM_SMEM);
        cudaFuncSetAttribute(k_gemm_tf32<false, false, true>,
                             cudaFuncAttributeMaxDynamicSharedMemorySize, GEMM_SMEM);
        attr_done = true;
    }

    const int fuse_items = N_NODES * 32;   // 1.6M >= E
    k_init<<<(N_NODES + 255) / 256, 256>>>((const int*)ei);
    k_hist_f2h<<<(fuse_items + 255) / 256, 256>>>(ei, x, E);
    k_scanfill<<<NPART, SCAN_B>>>();
    k_scatter<<<(E + 255) / 256, 256>>>(E);

    const int agg_blocks = (N_NODES * 32 + 255) / 256;

    // ---- layer 1: agg1 = S x (half gather) ; a1 = relu(agg1 @ W1 + b1) ----
    k_agg_h<false><<<agg_blocks, 256>>>(xh, buf128, nullptr);
    {
        dim3 grid(DIM_HID / 64, (N_NODES + 127) / 128);
        k_gemm_tf32<true, true, false><<<grid, 256, GEMM_SMEM>>>(
            buf128, W1, b1, a1, nullptr, N_NODES, DIM_IN, DIM_HID);
    }

    // ---- layer 2: t = a1 @ W2 (half out) ; out = S t + b2 ----
    {
        dim3 grid(DIM_OUT / 64, (N_NODES + 127) / 128);
        k_gemm_tf32<false, false, true><<<grid, 256, GEMM_SMEM>>>(
            a1, W2, nullptr, nullptr, th, N_NODES, DIM_HID, DIM_OUT);
    }
    k_agg_h<true><<<agg_blocks, 256>>>(th, out, b2);
}